// round 1
// baseline (speedup 1.0000x reference)
#include <cuda_runtime.h>

// GlobalNHC: Nose-Hoover chain thermostat, B=32 batches, N=131072 atoms, D=3, C=5 chain.
// Inputs (metadata order): pos[B,N,D], mom[B,N,D], mas[B,N], kbt[B], dtm[B],
//                          pos_nhc[B,C], mom_nhc[B,C], mas_nhc[B,C], stp (scalar)
// Output: concat( mom_out[B,N,D], pos_nhc_out[B,C], mom_nhc_out[B,C] ), float32.
//
// Algebraic collapse: mom only enters via KE = sum(mom^2/mas) and is only ever
// uniformly rescaled per batch. So: (1) reduce KE per batch, (2) run all 14
// Suzuki-Yoshida substeps as scalar chain math (KE *= s^2 per rescale),
// (3) apply the cumulative scale to mom once.

#define BB    32
#define NATM  131072
#define DDIM  3
#define CCH   5
#define NPER  (NATM * DDIM)      // 393216 elements per batch
#define NVEC  (NPER / 4)         // 98304 float4 per batch
#define NRESPA_ 2

__device__ double g_ke[BB];
__device__ float  g_scale[BB];

// ---------------------------------------------------------------------------
__global__ void nhc_zero_ke() {
    if (threadIdx.x < BB) g_ke[threadIdx.x] = 0.0;
}

// ---------------------------------------------------------------------------
// Pass 1: KE[b] = sum over (n,d) of mom^2 / mas   (double accumulation)
__global__ void nhc_ke_kernel(const float* __restrict__ mom,
                              const float* __restrict__ mas) {
    const int b = blockIdx.y;
    const float4* m4 = reinterpret_cast<const float4*>(mom) + (size_t)b * NVEC;
    const float*  ms = mas + (size_t)b * NATM;

    double acc = 0.0;
    for (int i = blockIdx.x * blockDim.x + threadIdx.x; i < NVEC;
         i += gridDim.x * blockDim.x) {
        float4 v = m4[i];
        int e = i * 4;
        acc += (double)(v.x * v.x / ms[(e    ) / 3]);
        acc += (double)(v.y * v.y / ms[(e + 1) / 3]);
        acc += (double)(v.z * v.z / ms[(e + 2) / 3]);
        acc += (double)(v.w * v.w / ms[(e + 3) / 3]);
    }

    __shared__ double sm[256];
    const int t = threadIdx.x;
    sm[t] = acc;
    __syncthreads();
    for (int s = 128; s > 0; s >>= 1) {
        if (t < s) sm[t] += sm[t + s];
        __syncthreads();
    }
    if (t == 0) atomicAdd(&g_ke[b], sm[0]);
}

// ---------------------------------------------------------------------------
// Pass 2: scalar chain dynamics, one thread per batch. All in double.
__global__ void nhc_chain_kernel(const float* __restrict__ kbt,
                                 const float* __restrict__ dtm,
                                 const float* __restrict__ pos_nhc,
                                 const float* __restrict__ mom_nhc,
                                 const float* __restrict__ mas_nhc,
                                 const float* __restrict__ stp_p,
                                 float* __restrict__ out_posnhc,
                                 float* __restrict__ out_momnhc) {
    const int b = threadIdx.x;
    if (b >= BB) return;

    const double wts[7] = {
        0.78451361047756, 0.235573213359357, -1.17767998417887,
        1.0 - 2.0 * (0.78451361047756 + 0.235573213359357 - 1.17767998417887),
        -1.17767998417887, 0.235573213359357, 0.78451361047756
    };

    double ke  = g_ke[b];
    const double kbT = (double)kbt[b];
    const double dt  = (double)dtm[b];
    const double stp = (double)stp_p[0];
    const double dof = (double)(NATM * DDIM);

    double pn[CCH], mn[CCH], mq[CCH];
    #pragma unroll
    for (int c = 0; c < CCH; c++) {
        pn[c] = (double)pos_nhc[b * CCH + c];
        mn[c] = (double)mom_nhc[b * CCH + c];
        mq[c] = (double)mas_nhc[b * CCH + c];
    }

    double cum = 1.0;

    for (int r = 0; r < NRESPA_; r++) {
        for (int iw = 0; iw < 7; iw++) {
            const double dea = dt * (stp * wts[iw] / (double)NRESPA_);
            double g[CCH], mc[CCH];

            // g from pre-step state (g[1..] depends only on entering mom_nhc)
            g[0] = ke - kbT * dof;
            #pragma unroll
            for (int j = 1; j < CCH; j++)
                g[j] = mn[j - 1] * mn[j - 1] / mq[j - 1] - kbT;

            #pragma unroll
            for (int c = 0; c < CCH; c++) mc[c] = mn[c];
            mc[CCH - 1] += g[CCH - 1] * (dea * 0.5);

            #pragma unroll
            for (int j = CCH - 2; j >= 0; j--) {
                double f = exp(-mc[j + 1] / mq[j + 1] * (dea * 0.25));
                mc[j] = (mc[j] * f + g[j] * (dea * 0.5)) * f;
            }

            // chain position drift + atomic momentum rescale (folded into KE/cum)
            #pragma unroll
            for (int c = 0; c < CCH; c++) pn[c] += mc[c] / mq[c] * dea;

            const double s = exp(-mc[0] / mq[0] * dea);
            cum *= s;
            ke  *= s * s;

            // second half: g0 from rescaled KE, g[1..] unchanged (original mn)
            g[0] = ke - kbT * dof;
            #pragma unroll
            for (int j = CCH - 2; j >= 0; j--) {
                double f = exp(-mc[j + 1] / mq[j + 1] * (dea * 0.25));
                mc[j] = (mc[j] * f + g[j] * (dea * 0.5)) * f;
            }
            mc[CCH - 1] += g[CCH - 1] * (dea * 0.5);

            #pragma unroll
            for (int c = 0; c < CCH; c++) mn[c] = mc[c];
        }
    }

    g_scale[b] = (float)cum;
    #pragma unroll
    for (int c = 0; c < CCH; c++) {
        out_posnhc[b * CCH + c] = (float)pn[c];
        out_momnhc[b * CCH + c] = (float)mn[c];
    }
}

// ---------------------------------------------------------------------------
// Pass 3: mom_out = mom * cum_scale[b]   (float4 streams; NPER % 4 == 0 so
// every float4 lies within one batch)
__global__ void nhc_scale_kernel(const float4* __restrict__ mom,
                                 float4* __restrict__ out) {
    const int i = blockIdx.x * blockDim.x + threadIdx.x;
    if (i >= BB * NVEC) return;
    const int b = i / NVEC;
    const float s = g_scale[b];
    float4 v = mom[i];
    v.x *= s; v.y *= s; v.z *= s; v.w *= s;
    out[i] = v;
}

// ---------------------------------------------------------------------------
extern "C" void kernel_launch(void* const* d_in, const int* in_sizes, int n_in,
                              void* d_out, int out_size) {
    // inputs: 0 pos, 1 mom, 2 mas, 3 kbt, 4 dtm, 5 pos_nhc, 6 mom_nhc, 7 mas_nhc, 8 stp
    const float* mom     = (const float*)d_in[1];
    const float* mas     = (const float*)d_in[2];
    const float* kbt     = (const float*)d_in[3];
    const float* dtm     = (const float*)d_in[4];
    const float* pos_nhc = (const float*)d_in[5];
    const float* mom_nhc = (const float*)d_in[6];
    const float* mas_nhc = (const float*)d_in[7];
    const float* stp     = (const float*)d_in[8];

    float* out = (float*)d_out;
    float* out_mom    = out;                          // [B, N, D]
    float* out_posnhc = out + (size_t)BB * NPER;      // [B, C]
    float* out_momnhc = out_posnhc + BB * CCH;        // [B, C]

    nhc_zero_ke<<<1, 32>>>();

    dim3 keGrid(48, BB);
    nhc_ke_kernel<<<keGrid, 256>>>(mom, mas);

    nhc_chain_kernel<<<1, 32>>>(kbt, dtm, pos_nhc, mom_nhc, mas_nhc, stp,
                                out_posnhc, out_momnhc);

    const int nv = BB * NVEC;                          // 3145728
    nhc_scale_kernel<<<(nv + 255) / 256, 256>>>(
        (const float4*)mom, (float4*)out_mom);
}

// round 2
// speedup vs baseline: 3.5066x; 3.5066x over previous
#include <cuda_runtime.h>

// GlobalNHC: Nose-Hoover chain thermostat, B=32, N=131072, D=3, C=5, NRESPA=2 x 7 SY weights.
// Collapse: mom enters only via KE = sum(mom^2/mas) and uniform per-batch rescale.
// Pass 1: per-batch KE reduction (block partials).  Pass 2: 32 serial fp32 chains
// (one per warp-leader), reduce partials via shuffles, fold rescale into KE (double)
// and a cumulative scale.  Pass 3: mom_out = mom * cum_scale[b].

#define BB    32
#define NATM  131072
#define DDIM  3
#define CCH   5
#define NPER  (NATM * DDIM)       // 393216 floats per batch
#define NVEC  (NPER / 4)          // 98304 float4 per batch
#define NQUAD (NATM / 4)          // 32768 atom-quads per batch
#define KEBLK 128                 // ke blocks per batch (grid.x)
#define NRESPA_ 2

__device__ double g_part[BB * KEBLK];
__device__ float  g_scale[BB];

// ---------------------------------------------------------------------------
// Pass 1: per-block partial KE.  Thread q handles atoms [4q,4q+4):
//   3 coalesced float4 mom loads + 1 float4 mas load, no int division.
__global__ void nhc_ke_kernel(const float4* __restrict__ mom4,
                              const float4* __restrict__ mas4) {
    const int b = blockIdx.y;
    const int q = blockIdx.x * blockDim.x + threadIdx.x;   // 0..NQUAD-1

    const float4* m = mom4 + (size_t)b * NVEC;
    const float4* a = mas4 + (size_t)b * NQUAD;

    float4 v0 = m[3 * q + 0];
    float4 v1 = m[3 * q + 1];
    float4 v2 = m[3 * q + 2];
    float4 ms = a[q];

    float s0 = v0.x * v0.x + v0.y * v0.y + v0.z * v0.z;   // atom 4q
    float s1 = v0.w * v0.w + v1.x * v1.x + v1.y * v1.y;   // atom 4q+1
    float s2 = v1.z * v1.z + v1.w * v1.w + v2.x * v2.x;   // atom 4q+2
    float s3 = v2.y * v2.y + v2.z * v2.z + v2.w * v2.w;   // atom 4q+3

    float acc = s0 / ms.x + s1 / ms.y + s2 / ms.z + s3 / ms.w;

    // block reduce in double
    __shared__ double sm[256];
    const int t = threadIdx.x;
    sm[t] = (double)acc;
    __syncthreads();
    #pragma unroll
    for (int s = 128; s > 0; s >>= 1) {
        if (t < s) sm[t] += sm[t + s];
        __syncthreads();
    }
    if (t == 0) g_part[b * KEBLK + blockIdx.x] = sm[0];
}

// ---------------------------------------------------------------------------
// Pass 2: one block, 32 warps.  Warp w reduces batch w's partials, then its
// lane 0 runs the 14-substep chain in fp32 (__expf), KE tracked in double.
__global__ void nhc_chain_kernel(const float* __restrict__ kbt,
                                 const float* __restrict__ dtm,
                                 const float* __restrict__ pos_nhc,
                                 const float* __restrict__ mom_nhc,
                                 const float* __restrict__ mas_nhc,
                                 const float* __restrict__ stp_p,
                                 float* __restrict__ out_posnhc,
                                 float* __restrict__ out_momnhc) {
    const int w = threadIdx.x >> 5;   // batch
    const int l = threadIdx.x & 31;

    double part = g_part[w * KEBLK + l]
                + g_part[w * KEBLK + 32 + l]
                + g_part[w * KEBLK + 64 + l]
                + g_part[w * KEBLK + 96 + l];
    #pragma unroll
    for (int off = 16; off > 0; off >>= 1)
        part += __shfl_down_sync(0xffffffffu, part, off);

    if (l != 0) return;
    const int b = w;

    const float wts[7] = {
        0.78451361047756f, 0.235573213359357f, -1.17767998417887f,
        (float)(1.0 - 2.0 * (0.78451361047756 + 0.235573213359357 - 1.17767998417887)),
        -1.17767998417887f, 0.235573213359357f, 0.78451361047756f
    };

    double ked = part;                                 // KE (double: cancels vs kbT*dof)
    const double kgd = (double)kbt[b] * (double)(NATM * DDIM);
    const float  kbT = kbt[b];
    const float  dts = dtm[b] * (stp_p[0] / (float)NRESPA_);

    float pn[CCH], mn[CCH], imq[CCH], mq_kbt_guard;
    (void)mq_kbt_guard;
    #pragma unroll
    for (int c = 0; c < CCH; c++) {
        pn[c]  = pos_nhc[b * CCH + c];
        mn[c]  = mom_nhc[b * CCH + c];
        imq[c] = 1.0f / mas_nhc[b * CCH + c];
    }

    double cum = 1.0;

    for (int r = 0; r < NRESPA_; r++) {
        #pragma unroll
        for (int iw = 0; iw < 7; iw++) {
            const float dea  = dts * wts[iw];
            const float dea2 = dea * 0.5f;
            const float dea4 = dea * 0.25f;

            float g[CCH], mc[CCH];
            g[0] = (float)(ked - kgd);
            #pragma unroll
            for (int j = 1; j < CCH; j++)
                g[j] = mn[j - 1] * mn[j - 1] * imq[j - 1] - kbT;

            #pragma unroll
            for (int c = 0; c < CCH; c++) mc[c] = mn[c];
            mc[CCH - 1] += g[CCH - 1] * dea2;

            #pragma unroll
            for (int j = CCH - 2; j >= 0; j--) {
                float f = __expf(-mc[j + 1] * imq[j + 1] * dea4);
                mc[j] = (mc[j] * f + g[j] * dea2) * f;
            }

            #pragma unroll
            for (int c = 0; c < CCH; c++) pn[c] += mc[c] * imq[c] * dea;

            const float s = __expf(-mc[0] * imq[0] * dea);
            cum *= (double)s;
            ked *= (double)s * (double)s;

            g[0] = (float)(ked - kgd);
            #pragma unroll
            for (int j = CCH - 2; j >= 0; j--) {
                float f = __expf(-mc[j + 1] * imq[j + 1] * dea4);
                mc[j] = (mc[j] * f + g[j] * dea2) * f;
            }
            mc[CCH - 1] += g[CCH - 1] * dea2;

            #pragma unroll
            for (int c = 0; c < CCH; c++) mn[c] = mc[c];
        }
    }

    g_scale[b] = (float)cum;
    #pragma unroll
    for (int c = 0; c < CCH; c++) {
        out_posnhc[b * CCH + c] = pn[c];
        out_momnhc[b * CCH + c] = mn[c];
    }
}

// ---------------------------------------------------------------------------
// Pass 3: mom_out = mom * cum_scale[b].  grid = (NVEC/256, B), exact cover.
__global__ void nhc_scale_kernel(const float4* __restrict__ mom,
                                 float4* __restrict__ out) {
    const int b = blockIdx.y;
    const size_t i = (size_t)b * NVEC + blockIdx.x * blockDim.x + threadIdx.x;
    const float s = g_scale[b];
    float4 v = mom[i];
    v.x *= s; v.y *= s; v.z *= s; v.w *= s;
    out[i] = v;
}

// ---------------------------------------------------------------------------
extern "C" void kernel_launch(void* const* d_in, const int* in_sizes, int n_in,
                              void* d_out, int out_size) {
    // inputs: 0 pos, 1 mom, 2 mas, 3 kbt, 4 dtm, 5 pos_nhc, 6 mom_nhc, 7 mas_nhc, 8 stp
    const float* mom     = (const float*)d_in[1];
    const float* mas     = (const float*)d_in[2];
    const float* kbt     = (const float*)d_in[3];
    const float* dtm     = (const float*)d_in[4];
    const float* pos_nhc = (const float*)d_in[5];
    const float* mom_nhc = (const float*)d_in[6];
    const float* mas_nhc = (const float*)d_in[7];
    const float* stp     = (const float*)d_in[8];

    float* out = (float*)d_out;
    float* out_mom    = out;                          // [B, N, D]
    float* out_posnhc = out + (size_t)BB * NPER;      // [B, C]
    float* out_momnhc = out_posnhc + BB * CCH;        // [B, C]

    dim3 keGrid(KEBLK, BB);                           // 128 x 32 blocks, 256 thr
    nhc_ke_kernel<<<keGrid, 256>>>((const float4*)mom, (const float4*)mas);

    nhc_chain_kernel<<<1, 1024>>>(kbt, dtm, pos_nhc, mom_nhc, mas_nhc, stp,
                                  out_posnhc, out_momnhc);

    dim3 scGrid(NVEC / 256, BB);                      // 384 x 32 blocks
    nhc_scale_kernel<<<scGrid, 256>>>((const float4*)mom, (float4*)out_mom);
}

// round 3
// speedup vs baseline: 4.1050x; 1.1707x over previous
#include <cuda_runtime.h>

// GlobalNHC: Nose-Hoover chain thermostat, B=32, N=131072, D=3, C=5, NRESPA=2 x 7 SY.
// Single persistent kernel: phase1 KE partials -> grid spin-sync -> per-block
// redundant chain math -> phase3 rescale (reads L2-hot from phase1).
//
// mom enters the integrator only via KE = sum(mom^2/mas) and a uniform per-batch
// rescale, so the 14 substeps collapse to scalar chain math with KE *= s^2.

#define BB     32
#define NATM   131072
#define DDIM   3
#define CCH    5
#define NPER   (NATM * DDIM)        // 393216 floats per batch
#define NVEC   (NPER / 4)           // 98304 float4 per batch
#define NQUAD  (NATM / 4)           // 32768 atom-quads per batch
#define GX     4                    // blocks per batch
#define NBLK   (GX * BB)            // 128 total blocks (all resident: 148 SMs)
#define QPB    (NQUAD / GX)         // 8192 quads per block
#define QPT    (QPB / 1024)         // 8 quads per thread
#define NRESPA_ 2

__device__ double       g_part[NBLK];       // per-block KE partials
__device__ unsigned int g_bar;              // monotonic arrival counter (never reset)

__global__ void __launch_bounds__(1024, 1)
nhc_fused_kernel(const float4* __restrict__ mom4,
                 const float4* __restrict__ mas4,
                 const float*  __restrict__ kbt,
                 const float*  __restrict__ dtm,
                 const float*  __restrict__ pos_nhc,
                 const float*  __restrict__ mom_nhc,
                 const float*  __restrict__ mas_nhc,
                 const float*  __restrict__ stp_p,
                 float4* __restrict__ out_mom4,
                 float*  __restrict__ out_posnhc,
                 float*  __restrict__ out_momnhc) {
    const int gx = blockIdx.x;                 // 0..GX-1
    const int b  = blockIdx.y;                 // batch
    const int t  = threadIdx.x;

    const int qbase = gx * QPB;                // first quad of this block (in batch b)
    const float4* m = mom4 + (size_t)b * NVEC;
    const float4* a = mas4 + (size_t)b * NQUAD;

    // ---------------- Phase 1: partial KE ----------------
    float acc = 0.0f;
    #pragma unroll
    for (int k = 0; k < QPT; k++) {
        const int q = qbase + t + k * 1024;
        float4 v0 = m[3 * q + 0];
        float4 v1 = m[3 * q + 1];
        float4 v2 = m[3 * q + 2];
        float4 ms = a[q];
        float s0 = v0.x * v0.x + v0.y * v0.y + v0.z * v0.z;
        float s1 = v0.w * v0.w + v1.x * v1.x + v1.y * v1.y;
        float s2 = v1.z * v1.z + v1.w * v1.w + v2.x * v2.x;
        float s3 = v2.y * v2.y + v2.z * v2.z + v2.w * v2.w;
        acc += s0 / ms.x + s1 / ms.y + s2 / ms.z + s3 / ms.w;
    }

    // warp reduce (float), then cross-warp in double
    #pragma unroll
    for (int off = 16; off > 0; off >>= 1)
        acc += __shfl_down_sync(0xffffffffu, acc, off);

    __shared__ double s_warp[32];
    __shared__ float  s_scale;
    const int wid = t >> 5, lid = t & 31;
    if (lid == 0) s_warp[wid] = (double)acc;
    __syncthreads();

    if (t == 0) {
        double tot = 0.0;
        #pragma unroll
        for (int i = 0; i < 32; i++) tot += s_warp[i];
        g_part[b * GX + gx] = tot;
        __threadfence();

        // ---------------- Grid sync (ticketed, replay-safe) ----------------
        unsigned int ticket = atomicAdd(&g_bar, 1u);
        unsigned int target = (ticket / NBLK + 1u) * NBLK;
        while (*((volatile unsigned int*)&g_bar) < target) __nanosleep(64);
        __threadfence();

        // ---------------- Phase 2: chain math for batch b ----------------
        double ked = g_part[b * GX + 0] + g_part[b * GX + 1]
                   + g_part[b * GX + 2] + g_part[b * GX + 3];

        const float wts[7] = {
            0.78451361047756f, 0.235573213359357f, -1.17767998417887f,
            (float)(1.0 - 2.0 * (0.78451361047756 + 0.235573213359357 - 1.17767998417887)),
            -1.17767998417887f, 0.235573213359357f, 0.78451361047756f
        };

        const double kgd = (double)kbt[b] * (double)(NATM * DDIM);
        const float  kbT = kbt[b];
        const float  dts = dtm[b] * (stp_p[0] / (float)NRESPA_);

        float pn[CCH], mn[CCH], imq[CCH];
        #pragma unroll
        for (int c = 0; c < CCH; c++) {
            pn[c]  = pos_nhc[b * CCH + c];
            mn[c]  = mom_nhc[b * CCH + c];
            imq[c] = 1.0f / mas_nhc[b * CCH + c];
        }

        double cum = 1.0;
        for (int r = 0; r < NRESPA_; r++) {
            #pragma unroll
            for (int iw = 0; iw < 7; iw++) {
                const float dea  = dts * wts[iw];
                const float dea2 = dea * 0.5f;
                const float dea4 = dea * 0.25f;

                float g[CCH], mc[CCH];
                g[0] = (float)(ked - kgd);
                #pragma unroll
                for (int j = 1; j < CCH; j++)
                    g[j] = mn[j - 1] * mn[j - 1] * imq[j - 1] - kbT;

                #pragma unroll
                for (int c = 0; c < CCH; c++) mc[c] = mn[c];
                mc[CCH - 1] += g[CCH - 1] * dea2;

                #pragma unroll
                for (int j = CCH - 2; j >= 0; j--) {
                    float f = __expf(-mc[j + 1] * imq[j + 1] * dea4);
                    mc[j] = (mc[j] * f + g[j] * dea2) * f;
                }

                #pragma unroll
                for (int c = 0; c < CCH; c++) pn[c] += mc[c] * imq[c] * dea;

                const float s = __expf(-mc[0] * imq[0] * dea);
                cum *= (double)s;
                ked *= (double)s * (double)s;

                g[0] = (float)(ked - kgd);
                #pragma unroll
                for (int j = CCH - 2; j >= 0; j--) {
                    float f = __expf(-mc[j + 1] * imq[j + 1] * dea4);
                    mc[j] = (mc[j] * f + g[j] * dea2) * f;
                }
                mc[CCH - 1] += g[CCH - 1] * dea2;

                #pragma unroll
                for (int c = 0; c < CCH; c++) mn[c] = mc[c];
            }
        }

        s_scale = (float)cum;
        if (gx == 0) {
            #pragma unroll
            for (int c = 0; c < CCH; c++) {
                out_posnhc[b * CCH + c] = pn[c];
                out_momnhc[b * CCH + c] = mn[c];
            }
        }
    }
    __syncthreads();

    // ---------------- Phase 3: rescale (reads are L2-hot) ----------------
    const float s = s_scale;
    float4* o = out_mom4 + (size_t)b * NVEC;
    #pragma unroll
    for (int k = 0; k < QPT; k++) {
        const int q = qbase + t + k * 1024;
        #pragma unroll
        for (int j = 0; j < 3; j++) {
            float4 v = m[3 * q + j];
            v.x *= s; v.y *= s; v.z *= s; v.w *= s;
            o[3 * q + j] = v;
        }
    }
}

// ---------------------------------------------------------------------------
extern "C" void kernel_launch(void* const* d_in, const int* in_sizes, int n_in,
                              void* d_out, int out_size) {
    // inputs: 0 pos, 1 mom, 2 mas, 3 kbt, 4 dtm, 5 pos_nhc, 6 mom_nhc, 7 mas_nhc, 8 stp
    const float* mom     = (const float*)d_in[1];
    const float* mas     = (const float*)d_in[2];
    const float* kbt     = (const float*)d_in[3];
    const float* dtm     = (const float*)d_in[4];
    const float* pos_nhc = (const float*)d_in[5];
    const float* mom_nhc = (const float*)d_in[6];
    const float* mas_nhc = (const float*)d_in[7];
    const float* stp     = (const float*)d_in[8];

    float* out = (float*)d_out;
    float* out_mom    = out;                          // [B, N, D]
    float* out_posnhc = out + (size_t)BB * NPER;      // [B, C]
    float* out_momnhc = out_posnhc + BB * CCH;        // [B, C]

    dim3 grid(GX, BB);                                // 128 blocks, all resident
    nhc_fused_kernel<<<grid, 1024>>>(
        (const float4*)mom, (const float4*)mas,
        kbt, dtm, pos_nhc, mom_nhc, mas_nhc, stp,
        (float4*)out_mom, out_posnhc, out_momnhc);
}

// round 4
// speedup vs baseline: 4.2835x; 1.0435x over previous
#include <cuda_runtime.h>

// GlobalNHC: Nose-Hoover chain thermostat, B=32, N=131072, D=3, C=5, NRESPA=2 x 7 SY.
// Persistent kernel, 256 blocks x 512 threads (2 CTAs/SM, all resident):
//   phase1 KE partials -> grid spin-sync -> per-block redundant chain math ->
//   phase3 rescale (reads L2-hot from phase1, streaming stores).
//
// mom enters the integrator only via KE = sum(mom^2/mas) and a uniform per-batch
// rescale, so the 14 substeps collapse to scalar chain math with KE *= s^2.

#define BB     32
#define NATM   131072
#define DDIM   3
#define CCH    5
#define NPER   (NATM * DDIM)        // 393216 floats per batch
#define NVEC   (NPER / 4)           // 98304 float4 per batch
#define NQUAD  (NATM / 4)           // 32768 atom-quads per batch
#define GX     8                    // blocks per batch
#define NBLK   (GX * BB)            // 256 total blocks (2 CTAs/SM resident)
#define TPB    512
#define QPB    (NQUAD / GX)         // 4096 quads per block
#define QPT    (QPB / TPB)          // 8 quads per thread
#define NRESPA_ 2

__device__ double       g_part[NBLK];       // per-block KE partials
__device__ unsigned int g_bar;              // monotonic arrival counter (never reset)

__device__ __forceinline__ void st_stream(float4* p, float4 v) {
    asm volatile("st.global.cs.v4.f32 [%0], {%1,%2,%3,%4};"
                 :: "l"(p), "f"(v.x), "f"(v.y), "f"(v.z), "f"(v.w) : "memory");
}

__global__ void __launch_bounds__(TPB, 2)
nhc_fused_kernel(const float4* __restrict__ mom4,
                 const float4* __restrict__ mas4,
                 const float*  __restrict__ kbt,
                 const float*  __restrict__ dtm,
                 const float*  __restrict__ pos_nhc,
                 const float*  __restrict__ mom_nhc,
                 const float*  __restrict__ mas_nhc,
                 const float*  __restrict__ stp_p,
                 float4* __restrict__ out_mom4,
                 float*  __restrict__ out_posnhc,
                 float*  __restrict__ out_momnhc) {
    const int gx = blockIdx.x;                 // 0..GX-1
    const int b  = blockIdx.y;                 // batch
    const int t  = threadIdx.x;

    const int qbase = gx * QPB;                // first quad of this block (in batch b)
    const float4* m = mom4 + (size_t)b * NVEC;
    const float4* a = mas4 + (size_t)b * NQUAD;

    // ---------------- Phase 1: partial KE ----------------
    float acc = 0.0f;
    #pragma unroll
    for (int k = 0; k < QPT; k++) {
        const int q = qbase + t + k * TPB;
        float4 v0 = m[3 * q + 0];
        float4 v1 = m[3 * q + 1];
        float4 v2 = m[3 * q + 2];
        float4 ms = a[q];
        float s0 = v0.x * v0.x + v0.y * v0.y + v0.z * v0.z;
        float s1 = v0.w * v0.w + v1.x * v1.x + v1.y * v1.y;
        float s2 = v1.z * v1.z + v1.w * v1.w + v2.x * v2.x;
        float s3 = v2.y * v2.y + v2.z * v2.z + v2.w * v2.w;
        acc += s0 / ms.x + s1 / ms.y + s2 / ms.z + s3 / ms.w;
    }

    // warp reduce (float), then cross-warp in double
    #pragma unroll
    for (int off = 16; off > 0; off >>= 1)
        acc += __shfl_down_sync(0xffffffffu, acc, off);

    __shared__ double s_warp[TPB / 32];
    __shared__ float  s_scale;
    const int wid = t >> 5, lid = t & 31;
    if (lid == 0) s_warp[wid] = (double)acc;
    __syncthreads();

    if (t == 0) {
        double tot = 0.0;
        #pragma unroll
        for (int i = 0; i < TPB / 32; i++) tot += s_warp[i];
        g_part[b * GX + gx] = tot;
        __threadfence();

        // ---------------- Grid sync (ticketed, replay-safe) ----------------
        unsigned int ticket = atomicAdd(&g_bar, 1u);
        unsigned int target = (ticket / NBLK + 1u) * NBLK;
        while (*((volatile unsigned int*)&g_bar) < target) __nanosleep(32);
        __threadfence();

        // ---------------- Phase 2: chain math for batch b ----------------
        double ked = 0.0;
        #pragma unroll
        for (int i = 0; i < GX; i++) ked += g_part[b * GX + i];

        const float wts[7] = {
            0.78451361047756f, 0.235573213359357f, -1.17767998417887f,
            (float)(1.0 - 2.0 * (0.78451361047756 + 0.235573213359357 - 1.17767998417887)),
            -1.17767998417887f, 0.235573213359357f, 0.78451361047756f
        };

        const double kgd = (double)kbt[b] * (double)(NATM * DDIM);
        const float  kbT = kbt[b];
        const float  dts = dtm[b] * (stp_p[0] / (float)NRESPA_);

        float pn[CCH], mn[CCH], imq[CCH];
        #pragma unroll
        for (int c = 0; c < CCH; c++) {
            pn[c]  = pos_nhc[b * CCH + c];
            mn[c]  = mom_nhc[b * CCH + c];
            imq[c] = 1.0f / mas_nhc[b * CCH + c];
        }

        double cum = 1.0;
        for (int r = 0; r < NRESPA_; r++) {
            #pragma unroll
            for (int iw = 0; iw < 7; iw++) {
                const float dea  = dts * wts[iw];
                const float dea2 = dea * 0.5f;
                const float dea4 = dea * 0.25f;

                float g[CCH], mc[CCH];
                g[0] = (float)(ked - kgd);
                #pragma unroll
                for (int j = 1; j < CCH; j++)
                    g[j] = mn[j - 1] * mn[j - 1] * imq[j - 1] - kbT;

                #pragma unroll
                for (int c = 0; c < CCH; c++) mc[c] = mn[c];
                mc[CCH - 1] += g[CCH - 1] * dea2;

                #pragma unroll
                for (int j = CCH - 2; j >= 0; j--) {
                    float f = __expf(-mc[j + 1] * imq[j + 1] * dea4);
                    mc[j] = (mc[j] * f + g[j] * dea2) * f;
                }

                #pragma unroll
                for (int c = 0; c < CCH; c++) pn[c] += mc[c] * imq[c] * dea;

                const float s = __expf(-mc[0] * imq[0] * dea);
                cum *= (double)s;
                ked *= (double)s * (double)s;

                g[0] = (float)(ked - kgd);
                #pragma unroll
                for (int j = CCH - 2; j >= 0; j--) {
                    float f = __expf(-mc[j + 1] * imq[j + 1] * dea4);
                    mc[j] = (mc[j] * f + g[j] * dea2) * f;
                }
                mc[CCH - 1] += g[CCH - 1] * dea2;

                #pragma unroll
                for (int c = 0; c < CCH; c++) mn[c] = mc[c];
            }
        }

        s_scale = (float)cum;
        if (gx == 0) {
            #pragma unroll
            for (int c = 0; c < CCH; c++) {
                out_posnhc[b * CCH + c] = pn[c];
                out_momnhc[b * CCH + c] = mn[c];
            }
        }
    }
    __syncthreads();

    // ---------------- Phase 3: rescale (reads L2-hot, streaming stores) ----
    const float s = s_scale;
    float4* o = out_mom4 + (size_t)b * NVEC;
    #pragma unroll
    for (int k = 0; k < QPT; k++) {
        const int q = qbase + t + k * TPB;
        #pragma unroll
        for (int j = 0; j < 3; j++) {
            float4 v = m[3 * q + j];
            v.x *= s; v.y *= s; v.z *= s; v.w *= s;
            st_stream(o + 3 * q + j, v);
        }
    }
}

// ---------------------------------------------------------------------------
extern "C" void kernel_launch(void* const* d_in, const int* in_sizes, int n_in,
                              void* d_out, int out_size) {
    // inputs: 0 pos, 1 mom, 2 mas, 3 kbt, 4 dtm, 5 pos_nhc, 6 mom_nhc, 7 mas_nhc, 8 stp
    const float* mom     = (const float*)d_in[1];
    const float* mas     = (const float*)d_in[2];
    const float* kbt     = (const float*)d_in[3];
    const float* dtm     = (const float*)d_in[4];
    const float* pos_nhc = (const float*)d_in[5];
    const float* mom_nhc = (const float*)d_in[6];
    const float* mas_nhc = (const float*)d_in[7];
    const float* stp     = (const float*)d_in[8];

    float* out = (float*)d_out;
    float* out_mom    = out;                          // [B, N, D]
    float* out_posnhc = out + (size_t)BB * NPER;      // [B, C]
    float* out_momnhc = out_posnhc + BB * CCH;        // [B, C]

    dim3 grid(GX, BB);                                // 256 blocks, all resident
    nhc_fused_kernel<<<grid, TPB>>>(
        (const float4*)mom, (const float4*)mas,
        kbt, dtm, pos_nhc, mom_nhc, mas_nhc, stp,
        (float4*)out_mom, out_posnhc, out_momnhc);
}

// round 5
// speedup vs baseline: 8.4019x; 1.9614x over previous
#include <cuda_runtime.h>

// GlobalNHC: Nose-Hoover chain thermostat, B=32, N=131072, D=3, C=5, NRESPA=2 x 7 SY.
// Persistent kernel, 128 blocks x 1024 threads (exactly 1 CTA/SM, balanced):
//   phase1: coalesced linear float4 KE reduction (magic /3 for atom mass assoc)
//   grid spin-sync -> per-block redundant chain math (fp32 + __expf, KE in double)
//   phase3: coalesced linear rescale, L2-hot reads, streaming stores.
//
// mom enters the integrator only via KE = sum(mom^2/mas) and a uniform per-batch
// rescale, so the 14 substeps collapse to scalar chain math with KE *= s^2.

#define BB     32
#define NATM   131072
#define DDIM   3
#define CCH    5
#define NPER   (NATM * DDIM)        // 393216 floats per batch
#define NVEC   (NPER / 4)           // 98304 float4 per batch
#define GX     4                    // blocks per batch
#define NBLK   (GX * BB)            // 128 blocks total (1 CTA/SM, all resident)
#define TPB    1024
#define V4PB   (NVEC / GX)          // 24576 float4 per block
#define V4PT   (V4PB / TPB)         // 24 float4 per thread
#define NRESPA_ 2

__device__ double       g_part[NBLK];       // per-block KE partials
__device__ unsigned int g_bar;              // monotonic arrival counter (never reset)

__device__ __forceinline__ void st_stream(float4* p, float4 v) {
    asm volatile("st.global.cs.v4.f32 [%0], {%1,%2,%3,%4};"
                 :: "l"(p), "f"(v.x), "f"(v.y), "f"(v.z), "f"(v.w) : "memory");
}

__global__ void __launch_bounds__(TPB, 1)
nhc_fused_kernel(const float4* __restrict__ mom4,
                 const float*  __restrict__ mas,
                 const float*  __restrict__ kbt,
                 const float*  __restrict__ dtm,
                 const float*  __restrict__ pos_nhc,
                 const float*  __restrict__ mom_nhc,
                 const float*  __restrict__ mas_nhc,
                 const float*  __restrict__ stp_p,
                 float4* __restrict__ out_mom4,
                 float*  __restrict__ out_posnhc,
                 float*  __restrict__ out_momnhc) {
    const int gx = blockIdx.x;                 // 0..GX-1
    const int b  = blockIdx.y;                 // batch
    const int t  = threadIdx.x;

    const float4* m    = mom4 + (size_t)b * NVEC;
    const float*  masb = mas  + (size_t)b * NATM;
    const int vbase = gx * V4PB;

    // ---------------- Phase 1: KE partial, fully coalesced ----------------
    // float4 at index L covers elements E=4L..4L+3; atom a = E/3, split by r=E%3:
    //   r=0: {x,y,z}->a, {w}->a+1   r=1: {x,y}->a, {z,w}->a+1   r=2: {x}->a, {y,z,w}->a+1
    float acc = 0.0f;
    #pragma unroll 4
    for (int k = 0; k < V4PT; k++) {
        const int L = vbase + k * TPB + t;
        float4 v = m[L];
        const unsigned E = 4u * (unsigned)L;
        const unsigned a = __umulhi(E, 0xAAAAAAABu) >> 1;   // E/3
        const unsigned r = E - 3u * a;                      // E%3
        float p  = v.x * v.x, q  = v.y * v.y;
        float u  = v.z * v.z, w2 = v.w * v.w;
        float cA = p, cB = w2;
        if (r < 2u)  cA += q; else cB += q;
        if (r == 0u) cA += u; else cB += u;
        float mA = masb[a], mB = masb[a + 1];
        acc += __fdividef(cA, mA) + __fdividef(cB, mB);
    }

    // warp reduce (float), then cross-warp in double
    #pragma unroll
    for (int off = 16; off > 0; off >>= 1)
        acc += __shfl_down_sync(0xffffffffu, acc, off);

    __shared__ double s_warp[TPB / 32];
    __shared__ float  s_scale;
    const int wid = t >> 5, lid = t & 31;
    if (lid == 0) s_warp[wid] = (double)acc;
    __syncthreads();

    if (t == 0) {
        double tot = 0.0;
        #pragma unroll
        for (int i = 0; i < TPB / 32; i++) tot += s_warp[i];
        g_part[b * GX + gx] = tot;
        __threadfence();

        // ---------------- Grid sync (ticketed, replay-safe) ----------------
        unsigned int ticket = atomicAdd(&g_bar, 1u);
        unsigned int target = (ticket / NBLK + 1u) * NBLK;
        while (*((volatile unsigned int*)&g_bar) < target) __nanosleep(32);
        __threadfence();

        // ---------------- Phase 2: chain math for batch b ----------------
        double ked = 0.0;
        #pragma unroll
        for (int i = 0; i < GX; i++) ked += g_part[b * GX + i];

        const float wts[7] = {
            0.78451361047756f, 0.235573213359357f, -1.17767998417887f,
            (float)(1.0 - 2.0 * (0.78451361047756 + 0.235573213359357 - 1.17767998417887)),
            -1.17767998417887f, 0.235573213359357f, 0.78451361047756f
        };

        const double kgd = (double)kbt[b] * (double)(NATM * DDIM);
        const float  kbT = kbt[b];
        const float  dts = dtm[b] * (stp_p[0] / (float)NRESPA_);

        float pn[CCH], mn[CCH], imq[CCH];
        #pragma unroll
        for (int c = 0; c < CCH; c++) {
            pn[c]  = pos_nhc[b * CCH + c];
            mn[c]  = mom_nhc[b * CCH + c];
            imq[c] = 1.0f / mas_nhc[b * CCH + c];
        }

        double cum = 1.0;
        for (int r = 0; r < NRESPA_; r++) {
            #pragma unroll
            for (int iw = 0; iw < 7; iw++) {
                const float dea  = dts * wts[iw];
                const float dea2 = dea * 0.5f;
                const float dea4 = dea * 0.25f;

                float g[CCH], mc[CCH];
                g[0] = (float)(ked - kgd);
                #pragma unroll
                for (int j = 1; j < CCH; j++)
                    g[j] = mn[j - 1] * mn[j - 1] * imq[j - 1] - kbT;

                #pragma unroll
                for (int c = 0; c < CCH; c++) mc[c] = mn[c];
                mc[CCH - 1] += g[CCH - 1] * dea2;

                #pragma unroll
                for (int j = CCH - 2; j >= 0; j--) {
                    float f = __expf(-mc[j + 1] * imq[j + 1] * dea4);
                    mc[j] = (mc[j] * f + g[j] * dea2) * f;
                }

                #pragma unroll
                for (int c = 0; c < CCH; c++) pn[c] += mc[c] * imq[c] * dea;

                const float s = __expf(-mc[0] * imq[0] * dea);
                cum *= (double)s;
                ked *= (double)s * (double)s;

                g[0] = (float)(ked - kgd);
                #pragma unroll
                for (int j = CCH - 2; j >= 0; j--) {
                    float f = __expf(-mc[j + 1] * imq[j + 1] * dea4);
                    mc[j] = (mc[j] * f + g[j] * dea2) * f;
                }
                mc[CCH - 1] += g[CCH - 1] * dea2;

                #pragma unroll
                for (int c = 0; c < CCH; c++) mn[c] = mc[c];
            }
        }

        s_scale = (float)cum;
        if (gx == 0) {
            #pragma unroll
            for (int c = 0; c < CCH; c++) {
                out_posnhc[b * CCH + c] = pn[c];
                out_momnhc[b * CCH + c] = mn[c];
            }
        }
    }
    __syncthreads();

    // ------- Phase 3: rescale, fully coalesced (L2-hot reads, st.cs) -------
    const float s = s_scale;
    float4* o = out_mom4 + (size_t)b * NVEC;
    #pragma unroll 4
    for (int k = 0; k < V4PT; k++) {
        const int L = vbase + k * TPB + t;
        float4 v = m[L];
        v.x *= s; v.y *= s; v.z *= s; v.w *= s;
        st_stream(o + L, v);
    }
}

// ---------------------------------------------------------------------------
extern "C" void kernel_launch(void* const* d_in, const int* in_sizes, int n_in,
                              void* d_out, int out_size) {
    // inputs: 0 pos, 1 mom, 2 mas, 3 kbt, 4 dtm, 5 pos_nhc, 6 mom_nhc, 7 mas_nhc, 8 stp
    const float* mom     = (const float*)d_in[1];
    const float* mas     = (const float*)d_in[2];
    const float* kbt     = (const float*)d_in[3];
    const float* dtm     = (const float*)d_in[4];
    const float* pos_nhc = (const float*)d_in[5];
    const float* mom_nhc = (const float*)d_in[6];
    const float* mas_nhc = (const float*)d_in[7];
    const float* stp     = (const float*)d_in[8];

    float* out = (float*)d_out;
    float* out_mom    = out;                          // [B, N, D]
    float* out_posnhc = out + (size_t)BB * NPER;      // [B, C]
    float* out_momnhc = out_posnhc + BB * CCH;        // [B, C]

    dim3 grid(GX, BB);                                // 128 blocks, 1 per SM
    nhc_fused_kernel<<<grid, TPB>>>(
        (const float4*)mom, mas,
        kbt, dtm, pos_nhc, mom_nhc, mas_nhc, stp,
        (float4*)out_mom, out_posnhc, out_momnhc);
}